// round 5
// baseline (speedup 1.0000x reference)
#include <cuda_runtime.h>
#include <cuda_bf16.h>

typedef unsigned long long ull;

// Problem-fixed capacities (N=50000, E=800000, d_hid=128, d_out=64, 64 graphs)
#define MAXN 50000
#define MAXE 800000

// ---------------- scratch (device globals; no runtime allocation) ----------
__device__ float g_xws1[MAXN * 128];   // dinv * (x @ W1)
__device__ float g_h[MAXN * 128];      // relu layer-1 output
__device__ float g_xws2[MAXN * 64];    // dinv * (h @ W2)
__device__ float g_dinv[MAXN];
__device__ int   g_cnt[MAXN];
__device__ int   g_cursor[MAXN];
__device__ int   g_rowptr[MAXN + 1];
__device__ int   g_colidx[MAXE];
__device__ int   g_src[MAXE];
__device__ int   g_dst[MAXE];
__device__ int   g_batch[MAXN];
__device__ float g_gsum[64 * 64];
__device__ float g_gcnt[64];
__device__ int   g_flag64;

// ---------------- f32x2 helpers (packed fp32 FMA, sm_100+) -----------------
__device__ __forceinline__ ull pack2(float a, float b) {
    ull r;
    asm("mov.b64 %0, {%1, %2};" : "=l"(r) : "f"(a), "f"(b));
    return r;
}
__device__ __forceinline__ float2 unpack2(ull v) {
    float2 r;
    asm("mov.b64 {%0, %1}, %2;" : "=f"(r.x), "=f"(r.y) : "l"(v));
    return r;
}
__device__ __forceinline__ void fma2(ull& d, ull a, ull b) {
    asm("fma.rn.f32x2 %0, %1, %2, %0;" : "+l"(d) : "l"(a), "l"(b));
}

// ---------------- setup kernels --------------------------------------------
__global__ void k_init(int N) {
    int i = blockIdx.x * blockDim.x + threadIdx.x;
    if (i < N) { g_cnt[i] = 0; g_cursor[i] = 0; }
    if (i < 64 * 64) g_gsum[i] = 0.0f;
    if (i < 64) g_gcnt[i] = 0.0f;
}

// Detect whether the index buffers are int64 or int32. Reads only the first
// 64 bytes (safe for both layouts). Real int64 graph indices are small; int32
// data read as int64 combines two random values -> huge with prob ~1.
__global__ void k_detect(const void* edges) {
    const long long* p = (const long long*)edges;
    int ok = 1;
    for (int i = 0; i < 8; i++) {
        long long v = p[i];
        if (v < 0 || v > 0x7fffffffLL) ok = 0;
    }
    g_flag64 = ok;
}

__global__ void k_conv_edges(const void* edges, int E, int N) {
    int e = blockIdx.x * blockDim.x + threadIdx.x;
    if (e >= E) return;
    long long s, d;
    if (g_flag64) {
        const long long* p = (const long long*)edges;
        s = p[e]; d = p[(size_t)E + e];
    } else {
        const int* p = (const int*)edges;
        s = p[e]; d = p[E + e];
    }
    if (s < 0) s = 0; if (s >= N) s = N - 1;
    if (d < 0) d = 0; if (d >= N) d = N - 1;
    g_src[e] = (int)s;
    g_dst[e] = (int)d;
}

__global__ void k_conv_batch(const void* bp, int N, int NG) {
    int i = blockIdx.x * blockDim.x + threadIdx.x;
    if (i >= N) return;
    long long b;
    if (g_flag64) b = ((const long long*)bp)[i];
    else          b = ((const int*)bp)[i];
    if (b < 0) b = 0; if (b >= NG) b = NG - 1;
    g_batch[i] = (int)b;
    atomicAdd(&g_gcnt[(int)b], 1.0f);
}

__global__ void k_count(int E) {
    int e = blockIdx.x * blockDim.x + threadIdx.x;
    if (e < E) atomicAdd(&g_cnt[g_dst[e]], 1);
}

// Single-block exclusive scan over g_cnt -> g_rowptr (warp-shuffle based).
__global__ void k_scan(int n) {
    __shared__ int warpsums[32];
    __shared__ int s_carry;
    int tid = threadIdx.x, lane = tid & 31, wid = tid >> 5;
    if (tid == 0) s_carry = 0;
    __syncthreads();
    for (int base = 0; base < n; base += 1024) {
        int i = base + tid;
        int v = (i < n) ? g_cnt[i] : 0;
        int incl = v;
        #pragma unroll
        for (int o = 1; o < 32; o <<= 1) {
            int t = __shfl_up_sync(0xffffffffu, incl, o);
            if (lane >= o) incl += t;
        }
        if (lane == 31) warpsums[wid] = incl;
        __syncthreads();
        if (wid == 0) {
            int w = warpsums[lane];
            int wincl = w;
            #pragma unroll
            for (int o = 1; o < 32; o <<= 1) {
                int t = __shfl_up_sync(0xffffffffu, wincl, o);
                if (lane >= o) wincl += t;
            }
            warpsums[lane] = wincl - w;  // exclusive warp offsets
        }
        __syncthreads();
        int excl = (incl - v) + warpsums[wid] + s_carry;
        if (i < n) g_rowptr[i] = excl;
        __syncthreads();
        if (tid == 1023) s_carry = excl + v;
        __syncthreads();
    }
    if (threadIdx.x == 0) g_rowptr[n] = s_carry;
}

__global__ void k_dinv(int N) {
    int i = blockIdx.x * blockDim.x + threadIdx.x;
    if (i < N) g_dinv[i] = rsqrtf((float)g_cnt[i] + 1.0f);  // +1 self loop
}

__global__ void k_fill(int E) {
    int e = blockIdx.x * blockDim.x + threadIdx.x;
    if (e >= E) return;
    int d = g_dst[e];
    int pos = atomicAdd(&g_cursor[d], 1);
    g_colidx[g_rowptr[d] + pos] = g_src[e];
}

// ---------------- GEMM: out[m][:] = dinv[m] * (X[m][:] @ W) ----------------
// BM=128, BK=32, thread tile 8x8, packed f32x2 FMAs.
template <int BN, int NT>
__global__ __launch_bounds__(NT, 1)
void gemm_kernel(const float* __restrict__ X, const float* __restrict__ W,
                 float* __restrict__ out, int M, int K) {
    constexpr int BM = 128, BK = 32;
    __shared__ float xs[BK][BM + 4];   // transposed x tile, padded
    __shared__ float ws[BK][BN];

    int tid = threadIdx.x;
    int cx = tid % (BN / 8);
    int cy = tid / (BN / 8);
    int m0 = blockIdx.x * BM;

    ull acc[8][4];
    #pragma unroll
    for (int i = 0; i < 8; i++)
        #pragma unroll
        for (int j = 0; j < 4; j++) acc[i][j] = 0ull;

    for (int kt = 0; kt < K; kt += BK) {
        // load X tile (transposed into smem)
        #pragma unroll
        for (int l = 0; l < (BM * BK / 4) / NT; l++) {
            int idx = tid + l * NT;
            int r = idx >> 3;       // 8 float4 per row (BK=32)
            int kq = idx & 7;
            int grow = m0 + r;
            if (grow >= M) grow = M - 1;
            float4 v = __ldg((const float4*)(X + (size_t)grow * K + kt + kq * 4));
            xs[kq * 4 + 0][r] = v.x;
            xs[kq * 4 + 1][r] = v.y;
            xs[kq * 4 + 2][r] = v.z;
            xs[kq * 4 + 3][r] = v.w;
        }
        // load W tile
        #pragma unroll
        for (int l = 0; l < (BK * BN / 4) / NT; l++) {
            int idx = tid + l * NT;
            int wr = idx / (BN / 4);
            int wc = idx % (BN / 4);
            float4 v = __ldg((const float4*)(W + (size_t)(kt + wr) * BN + wc * 4));
            *(float4*)&ws[wr][wc * 4] = v;
        }
        __syncthreads();

        #pragma unroll
        for (int kk = 0; kk < BK; kk++) {
            float4 a0 = *(const float4*)&xs[kk][cy * 8];
            float4 a1 = *(const float4*)&xs[kk][cy * 8 + 4];
            float4 b0 = *(const float4*)&ws[kk][cx * 8];
            float4 b1 = *(const float4*)&ws[kk][cx * 8 + 4];
            ull bb0 = pack2(b0.x, b0.y), bb1 = pack2(b0.z, b0.w);
            ull bb2 = pack2(b1.x, b1.y), bb3 = pack2(b1.z, b1.w);
            float a[8] = {a0.x, a0.y, a0.z, a0.w, a1.x, a1.y, a1.z, a1.w};
            #pragma unroll
            for (int i = 0; i < 8; i++) {
                ull ap = pack2(a[i], a[i]);
                fma2(acc[i][0], ap, bb0);
                fma2(acc[i][1], ap, bb1);
                fma2(acc[i][2], ap, bb2);
                fma2(acc[i][3], ap, bb3);
            }
        }
        __syncthreads();
    }

    #pragma unroll
    for (int i = 0; i < 8; i++) {
        int r = m0 + cy * 8 + i;
        if (r < M) {
            float di = g_dinv[r];
            float2 p0 = unpack2(acc[i][0]);
            float2 p1 = unpack2(acc[i][1]);
            float2 p2 = unpack2(acc[i][2]);
            float2 p3 = unpack2(acc[i][3]);
            float4 o0 = make_float4(di * p0.x, di * p0.y, di * p1.x, di * p1.y);
            float4 o1 = make_float4(di * p2.x, di * p2.y, di * p3.x, di * p3.y);
            *(float4*)(out + (size_t)r * BN + cx * 8) = o0;
            *(float4*)(out + (size_t)r * BN + cx * 8 + 4) = o1;
        }
    }
}

// ---------------- layer-1 aggregation: warp per node, F=128, ReLU ----------
__global__ __launch_bounds__(256)
void agg1_kernel(const float* __restrict__ xws, const float* __restrict__ bias,
                 float* __restrict__ out, int M) {
    int node = blockIdx.x * 8 + (threadIdx.x >> 5);
    if (node >= M) return;
    int lane = threadIdx.x & 31;
    const float4* base = (const float4*)xws;
    size_t off = (size_t)node * 32 + lane;
    float4 acc = __ldg(base + off);           // self loop
    int s = g_rowptr[node], e = g_rowptr[node + 1];
    int i = s;
    for (; i + 2 <= e; i += 2) {
        int s0 = g_colidx[i], s1 = g_colidx[i + 1];
        float4 v0 = __ldg(base + (size_t)s0 * 32 + lane);
        float4 v1 = __ldg(base + (size_t)s1 * 32 + lane);
        acc.x += v0.x; acc.y += v0.y; acc.z += v0.z; acc.w += v0.w;
        acc.x += v1.x; acc.y += v1.y; acc.z += v1.z; acc.w += v1.w;
    }
    if (i < e) {
        int s0 = g_colidx[i];
        float4 v0 = __ldg(base + (size_t)s0 * 32 + lane);
        acc.x += v0.x; acc.y += v0.y; acc.z += v0.z; acc.w += v0.w;
    }
    float di = g_dinv[node];
    float4 bv = __ldg((const float4*)bias + lane);
    float4 r;
    r.x = fmaxf(di * acc.x + bv.x, 0.0f);
    r.y = fmaxf(di * acc.y + bv.y, 0.0f);
    r.z = fmaxf(di * acc.z + bv.z, 0.0f);
    r.w = fmaxf(di * acc.w + bv.w, 0.0f);
    ((float4*)out)[off] = r;
}

// ---------------- layer-2 aggregation + fused mean-pool (sums) -------------
// F=64: lane handles 2 cols. Per-block smem pool exploits sorted batch to
// flush only the touched graph range.
__global__ __launch_bounds__(256)
void agg2_pool_kernel(const float* __restrict__ xws, const float* __restrict__ bias,
                      int M) {
    __shared__ float spool[64 * 64];
    __shared__ int s_gmin, s_gmax;
    int tid = threadIdx.x;
    for (int j = tid; j < 64 * 64; j += 256) spool[j] = 0.0f;
    if (tid == 0) { s_gmin = 1 << 30; s_gmax = -1; }
    __syncthreads();

    int node = blockIdx.x * 8 + (tid >> 5);
    int lane = tid & 31;
    if (node < M) {
        const float2* base = (const float2*)xws;
        size_t off = (size_t)node * 32 + lane;
        float2 acc = __ldg(base + off);       // self loop
        int s = g_rowptr[node], e = g_rowptr[node + 1];
        int i = s;
        for (; i + 2 <= e; i += 2) {
            int s0 = g_colidx[i], s1 = g_colidx[i + 1];
            float2 v0 = __ldg(base + (size_t)s0 * 32 + lane);
            float2 v1 = __ldg(base + (size_t)s1 * 32 + lane);
            acc.x += v0.x; acc.y += v0.y;
            acc.x += v1.x; acc.y += v1.y;
        }
        if (i < e) {
            int s0 = g_colidx[i];
            float2 v0 = __ldg(base + (size_t)s0 * 32 + lane);
            acc.x += v0.x; acc.y += v0.y;
        }
        float di = g_dinv[node];
        float2 bv = __ldg((const float2*)bias + lane);
        float rx = di * acc.x + bv.x;
        float ry = di * acc.y + bv.y;
        int g = g_batch[node];
        if (lane == 0) { atomicMin(&s_gmin, g); atomicMax(&s_gmax, g); }
        atomicAdd(&spool[g * 64 + lane * 2], rx);
        atomicAdd(&spool[g * 64 + lane * 2 + 1], ry);
    }
    __syncthreads();
    int gmin = s_gmin, gmax = s_gmax;
    if (gmax >= gmin) {
        int lo = gmin * 64;
        int cnt = (gmax - gmin + 1) * 64;
        for (int j = tid; j < cnt; j += 256)
            atomicAdd(&g_gsum[lo + j], spool[lo + j]);
    }
}

__global__ void k_final(float* __restrict__ out, int n) {
    int i = blockIdx.x * blockDim.x + threadIdx.x;
    if (i < n) out[i] = g_gsum[i] / fmaxf(g_gcnt[i >> 6], 1.0f);
}

// ---------------- launch ----------------------------------------------------
extern "C" void kernel_launch(void* const* d_in, const int* in_sizes, int n_in,
                              void* d_out, int out_size) {
    const float* x  = (const float*)d_in[0];
    const void*  ei = d_in[1];
    const void*  bp = d_in[2];
    const float* W1 = (const float*)d_in[3];
    const float* b1 = (const float*)d_in[4];
    const float* W2 = (const float*)d_in[5];
    const float* b2 = (const float*)d_in[6];
    float* out = (float*)d_out;

    int N    = in_sizes[2];          // 50000
    int E    = in_sizes[1] / 2;      // 800000
    int dhid = in_sizes[4];          // 128
    int dout = in_sizes[6];          // 64
    int din  = in_sizes[0] / N;      // 128
    int NG   = out_size / dout;      // 64

    float *p_xws1, *p_h, *p_xws2;
    cudaGetSymbolAddress((void**)&p_xws1, g_xws1);
    cudaGetSymbolAddress((void**)&p_h,    g_h);
    cudaGetSymbolAddress((void**)&p_xws2, g_xws2);

    int nbN = (N + 255) / 256;
    int nbE = (E + 255) / 256;
    int nbI = ((N > 4096 ? N : 4096) + 255) / 256;

    k_init<<<nbI, 256>>>(N);
    k_detect<<<1, 1>>>(ei);
    k_conv_edges<<<nbE, 256>>>(ei, E, N);
    k_conv_batch<<<nbN, 256>>>(bp, N, NG);
    k_count<<<nbE, 256>>>(E);
    k_scan<<<1, 1024>>>(N);
    k_dinv<<<nbN, 256>>>(N);
    k_fill<<<nbE, 256>>>(E);

    // layer 1
    gemm_kernel<128, 256><<<(N + 127) / 128, 256>>>(x, W1, p_xws1, N, din);
    agg1_kernel<<<(N + 7) / 8, 256>>>(p_xws1, b1, p_h, N);

    // layer 2 + fused pooling
    gemm_kernel<64, 128><<<(N + 127) / 128, 128>>>(p_h, W2, p_xws2, N, dhid);
    agg2_pool_kernel<<<(N + 7) / 8, 256>>>(p_xws2, b2, N);

    k_final<<<(out_size + 255) / 256, 256>>>(out, out_size);
}

// round 6
// speedup vs baseline: 1.8524x; 1.8524x over previous
#include <cuda_runtime.h>
#include <cuda_bf16.h>

typedef unsigned long long ull;

// Problem-fixed capacities (N=50000, E=800000, d_hid=128, d_out=64, 64 graphs)
#define MAXN 50000
#define MAXE 800000
#define SCAN_CHUNK 512

// ---------------- scratch (device globals; no runtime allocation) ----------
__device__ float g_xws1[MAXN * 128];   // dinv * (x @ W1)
__device__ float g_h[MAXN * 128];      // relu layer-1 output
__device__ float g_xws2[MAXN * 64];    // dinv * (h @ W2)
__device__ float g_dinv[MAXN];
__device__ int   g_cnt[MAXN];
__device__ int   g_cursor[MAXN];
__device__ int   g_rowptr[MAXN + 1];
__device__ int   g_colidx[MAXE];
__device__ int   g_src[MAXE];
__device__ int   g_dst[MAXE];
__device__ int   g_batch[MAXN];
__device__ float g_gsum[64 * 64];
__device__ float g_gcnt[64];
__device__ int   g_flag64;
__device__ int   g_bsum[128];
__device__ int   g_boff[128];

// ---------------- f32x2 helpers (packed fp32 FMA, sm_100+) -----------------
__device__ __forceinline__ ull pack2(float a, float b) {
    ull r;
    asm("mov.b64 %0, {%1, %2};" : "=l"(r) : "f"(a), "f"(b));
    return r;
}
__device__ __forceinline__ float2 unpack2(ull v) {
    float2 r;
    asm("mov.b64 {%0, %1}, %2;" : "=f"(r.x), "=f"(r.y) : "l"(v));
    return r;
}
__device__ __forceinline__ void fma2(ull& d, ull a, ull b) {
    asm("fma.rn.f32x2 %0, %1, %2, %0;" : "+l"(d) : "l"(a), "l"(b));
}

// ---------------- setup kernels --------------------------------------------
__global__ void k_init(int N) {
    int i = blockIdx.x * blockDim.x + threadIdx.x;
    if (i < N) { g_cnt[i] = 0; g_cursor[i] = 0; }
    if (i < 64 * 64) g_gsum[i] = 0.0f;
    if (i < 64) g_gcnt[i] = 0.0f;
}

// Detect int64 vs int32 index buffers. Batched loads for MLP.
__global__ void k_detect(const void* edges) {
    const long long* p = (const long long*)edges;
    long long v[8];
    #pragma unroll
    for (int i = 0; i < 8; i++) v[i] = p[i];
    int ok = 1;
    #pragma unroll
    for (int i = 0; i < 8; i++)
        if (v[i] < 0 || v[i] > 0x7fffffffLL) ok = 0;
    g_flag64 = ok;
}

// Edge conversion fused with degree counting (one pass over E).
__global__ void k_conv_edges_count(const void* edges, int E, int N) {
    int e = blockIdx.x * blockDim.x + threadIdx.x;
    if (e >= E) return;
    long long s, d;
    if (g_flag64) {
        const long long* p = (const long long*)edges;
        s = p[e]; d = p[(size_t)E + e];
    } else {
        const int* p = (const int*)edges;
        s = p[e]; d = p[E + e];
    }
    if (s < 0) s = 0; if (s >= N) s = N - 1;
    if (d < 0) d = 0; if (d >= N) d = N - 1;
    g_src[e] = (int)s;
    g_dst[e] = (int)d;
    atomicAdd(&g_cnt[(int)d], 1);
}

// Batch conversion + per-block smem histogram (kills 64-address float-atomic
// contention that cost 44us last round).
__global__ void k_conv_batch(const void* bp, int N, int NG) {
    __shared__ int sh[64];
    int tid = threadIdx.x;
    if (tid < 64) sh[tid] = 0;
    __syncthreads();
    int i = blockIdx.x * blockDim.x + tid;
    if (i < N) {
        long long b;
        if (g_flag64) b = ((const long long*)bp)[i];
        else          b = ((const int*)bp)[i];
        if (b < 0) b = 0; if (b >= NG) b = NG - 1;
        g_batch[i] = (int)b;
        atomicAdd(&sh[(int)b], 1);
    }
    __syncthreads();
    if (tid < 64 && sh[tid] != 0)
        atomicAdd(&g_gcnt[tid], (float)sh[tid]);
}

// ---------------- 3-phase parallel scan over g_cnt -> g_rowptr -------------
__global__ void k_scanA(int n) {   // per-block partial sums
    __shared__ int ws[16];
    int tid = threadIdx.x, lane = tid & 31, wid = tid >> 5;
    int i = blockIdx.x * SCAN_CHUNK + tid;
    int v = (i < n) ? g_cnt[i] : 0;
    #pragma unroll
    for (int o = 16; o; o >>= 1) v += __shfl_down_sync(0xffffffffu, v, o);
    if (lane == 0) ws[wid] = v;
    __syncthreads();
    if (wid == 0) {
        int t = (lane < 16) ? ws[lane] : 0;
        #pragma unroll
        for (int o = 16; o; o >>= 1) t += __shfl_down_sync(0xffffffffu, t, o);
        if (lane == 0) g_bsum[blockIdx.x] = t;
    }
}

__global__ void k_scanB(int nb) {  // exclusive scan of <=128 partials
    __shared__ int ws[4];
    __shared__ int woff[4];
    int tid = threadIdx.x, lane = tid & 31, wid = tid >> 5;
    int v = (tid < nb) ? g_bsum[tid] : 0;
    int incl = v;
    #pragma unroll
    for (int o = 1; o < 32; o <<= 1) {
        int t = __shfl_up_sync(0xffffffffu, incl, o);
        if (lane >= o) incl += t;
    }
    if (lane == 31) ws[wid] = incl;
    __syncthreads();
    if (tid == 0) {
        int acc = 0;
        #pragma unroll
        for (int w = 0; w < 4; w++) { woff[w] = acc; acc += ws[w]; }
    }
    __syncthreads();
    if (tid < nb) g_boff[tid] = incl - v + woff[wid];
}

__global__ void k_scanC(int n) {   // final scan + dinv fused
    __shared__ int ws[16];
    __shared__ int woff[16];
    int tid = threadIdx.x, lane = tid & 31, wid = tid >> 5;
    int i = blockIdx.x * SCAN_CHUNK + tid;
    int v = (i < n) ? g_cnt[i] : 0;
    int incl = v;
    #pragma unroll
    for (int o = 1; o < 32; o <<= 1) {
        int t = __shfl_up_sync(0xffffffffu, incl, o);
        if (lane >= o) incl += t;
    }
    if (lane == 31) ws[wid] = incl;
    __syncthreads();
    if (wid == 0 && lane < 16) {
        int w = ws[lane];
        int wincl = w;
        #pragma unroll
        for (int o = 1; o < 16; o <<= 1) {
            int t = __shfl_up_sync(0x0000ffffu, wincl, o);
            if (lane >= o) wincl += t;
        }
        woff[lane] = wincl - w;
    }
    __syncthreads();
    int excl = (incl - v) + woff[wid] + g_boff[blockIdx.x];
    if (i < n) {
        g_rowptr[i] = excl;
        g_dinv[i] = rsqrtf((float)v + 1.0f);   // +1 self loop
    }
    if (i == n - 1) g_rowptr[n] = excl + v;
}

__global__ void k_fill(int E) {
    int e = blockIdx.x * blockDim.x + threadIdx.x;
    if (e >= E) return;
    int d = g_dst[e];
    int pos = atomicAdd(&g_cursor[d], 1);
    g_colidx[g_rowptr[d] + pos] = g_src[e];
}

// ---------------- GEMM: out[m][:] = dinv[m] * (X[m][:] @ W) ----------------
template <int BN, int NT>
__global__ __launch_bounds__(NT, 1)
void gemm_kernel(const float* __restrict__ X, const float* __restrict__ W,
                 float* __restrict__ out, int M, int K) {
    constexpr int BM = 128, BK = 32;
    __shared__ float xs[BK][BM + 4];
    __shared__ float ws[BK][BN];

    int tid = threadIdx.x;
    int cx = tid % (BN / 8);
    int cy = tid / (BN / 8);
    int m0 = blockIdx.x * BM;

    ull acc[8][4];
    #pragma unroll
    for (int i = 0; i < 8; i++)
        #pragma unroll
        for (int j = 0; j < 4; j++) acc[i][j] = 0ull;

    for (int kt = 0; kt < K; kt += BK) {
        #pragma unroll
        for (int l = 0; l < (BM * BK / 4) / NT; l++) {
            int idx = tid + l * NT;
            int r = idx >> 3;
            int kq = idx & 7;
            int grow = m0 + r;
            if (grow >= M) grow = M - 1;
            float4 v = __ldg((const float4*)(X + (size_t)grow * K + kt + kq * 4));
            xs[kq * 4 + 0][r] = v.x;
            xs[kq * 4 + 1][r] = v.y;
            xs[kq * 4 + 2][r] = v.z;
            xs[kq * 4 + 3][r] = v.w;
        }
        #pragma unroll
        for (int l = 0; l < (BK * BN / 4) / NT; l++) {
            int idx = tid + l * NT;
            int wr = idx / (BN / 4);
            int wc = idx % (BN / 4);
            float4 v = __ldg((const float4*)(W + (size_t)(kt + wr) * BN + wc * 4));
            *(float4*)&ws[wr][wc * 4] = v;
        }
        __syncthreads();

        #pragma unroll
        for (int kk = 0; kk < BK; kk++) {
            float4 a0 = *(const float4*)&xs[kk][cy * 8];
            float4 a1 = *(const float4*)&xs[kk][cy * 8 + 4];
            float4 b0 = *(const float4*)&ws[kk][cx * 8];
            float4 b1 = *(const float4*)&ws[kk][cx * 8 + 4];
            ull bb0 = pack2(b0.x, b0.y), bb1 = pack2(b0.z, b0.w);
            ull bb2 = pack2(b1.x, b1.y), bb3 = pack2(b1.z, b1.w);
            float a[8] = {a0.x, a0.y, a0.z, a0.w, a1.x, a1.y, a1.z, a1.w};
            #pragma unroll
            for (int i = 0; i < 8; i++) {
                ull ap = pack2(a[i], a[i]);
                fma2(acc[i][0], ap, bb0);
                fma2(acc[i][1], ap, bb1);
                fma2(acc[i][2], ap, bb2);
                fma2(acc[i][3], ap, bb3);
            }
        }
        __syncthreads();
    }

    #pragma unroll
    for (int i = 0; i < 8; i++) {
        int r = m0 + cy * 8 + i;
        if (r < M) {
            float di = g_dinv[r];
            float2 p0 = unpack2(acc[i][0]);
            float2 p1 = unpack2(acc[i][1]);
            float2 p2 = unpack2(acc[i][2]);
            float2 p3 = unpack2(acc[i][3]);
            float4 o0 = make_float4(di * p0.x, di * p0.y, di * p1.x, di * p1.y);
            float4 o1 = make_float4(di * p2.x, di * p2.y, di * p3.x, di * p3.y);
            *(float4*)(out + (size_t)r * BN + cx * 8) = o0;
            *(float4*)(out + (size_t)r * BN + cx * 8 + 4) = o1;
        }
    }
}

// ---------------- layer-1 aggregation: warp per node, F=128, ReLU ----------
// Neighbor indices: one coalesced LDG per 32 edges, broadcast via shfl.
// 4 independent accumulators -> gather MLP >= 4.
__global__ __launch_bounds__(256)
void agg1_kernel(const float* __restrict__ xws, const float* __restrict__ bias,
                 float* __restrict__ out, int M) {
    int node = blockIdx.x * 8 + (threadIdx.x >> 5);
    if (node >= M) return;
    int lane = threadIdx.x & 31;
    const float4* base = (const float4*)xws;
    size_t off = (size_t)node * 32 + lane;
    float4 a0 = __ldg(base + off);           // self loop
    float4 a1 = make_float4(0.f, 0.f, 0.f, 0.f);
    float4 a2 = make_float4(0.f, 0.f, 0.f, 0.f);
    float4 a3 = make_float4(0.f, 0.f, 0.f, 0.f);
    int s = g_rowptr[node], e = g_rowptr[node + 1];

    for (int cs = s; cs < e; cs += 32) {
        int cnt = e - cs; if (cnt > 32) cnt = 32;
        int idx = (cs + lane < e) ? g_colidx[cs + lane] : 0;
        int j = 0;
        for (; j + 4 <= cnt; j += 4) {
            int s0 = __shfl_sync(0xffffffffu, idx, j);
            int s1 = __shfl_sync(0xffffffffu, idx, j + 1);
            int s2 = __shfl_sync(0xffffffffu, idx, j + 2);
            int s3 = __shfl_sync(0xffffffffu, idx, j + 3);
            float4 v0 = __ldg(base + (size_t)s0 * 32 + lane);
            float4 v1 = __ldg(base + (size_t)s1 * 32 + lane);
            float4 v2 = __ldg(base + (size_t)s2 * 32 + lane);
            float4 v3 = __ldg(base + (size_t)s3 * 32 + lane);
            a0.x += v0.x; a0.y += v0.y; a0.z += v0.z; a0.w += v0.w;
            a1.x += v1.x; a1.y += v1.y; a1.z += v1.z; a1.w += v1.w;
            a2.x += v2.x; a2.y += v2.y; a2.z += v2.z; a2.w += v2.w;
            a3.x += v3.x; a3.y += v3.y; a3.z += v3.z; a3.w += v3.w;
        }
        for (; j < cnt; j++) {
            int s0 = __shfl_sync(0xffffffffu, idx, j);
            float4 v0 = __ldg(base + (size_t)s0 * 32 + lane);
            a1.x += v0.x; a1.y += v0.y; a1.z += v0.z; a1.w += v0.w;
        }
    }
    float4 acc;
    acc.x = (a0.x + a1.x) + (a2.x + a3.x);
    acc.y = (a0.y + a1.y) + (a2.y + a3.y);
    acc.z = (a0.z + a1.z) + (a2.z + a3.z);
    acc.w = (a0.w + a1.w) + (a2.w + a3.w);
    float di = g_dinv[node];
    float4 bv = __ldg((const float4*)bias + lane);
    float4 r;
    r.x = fmaxf(di * acc.x + bv.x, 0.0f);
    r.y = fmaxf(di * acc.y + bv.y, 0.0f);
    r.z = fmaxf(di * acc.z + bv.z, 0.0f);
    r.w = fmaxf(di * acc.w + bv.w, 0.0f);
    ((float4*)out)[off] = r;
}

// ---------------- layer-2 aggregation + fused mean-pool (sums) -------------
__global__ __launch_bounds__(256)
void agg2_pool_kernel(const float* __restrict__ xws, const float* __restrict__ bias,
                      int M) {
    __shared__ float spool[64 * 64];
    __shared__ int s_gmin, s_gmax;
    int tid = threadIdx.x;
    for (int j = tid; j < 64 * 64; j += 256) spool[j] = 0.0f;
    if (tid == 0) { s_gmin = 1 << 30; s_gmax = -1; }
    __syncthreads();

    int node = blockIdx.x * 8 + (tid >> 5);
    int lane = tid & 31;
    if (node < M) {
        const float2* base = (const float2*)xws;
        size_t off = (size_t)node * 32 + lane;
        float2 a0 = __ldg(base + off);       // self loop
        float2 a1 = make_float2(0.f, 0.f);
        float2 a2 = make_float2(0.f, 0.f);
        float2 a3 = make_float2(0.f, 0.f);
        int s = g_rowptr[node], e = g_rowptr[node + 1];
        for (int cs = s; cs < e; cs += 32) {
            int cnt = e - cs; if (cnt > 32) cnt = 32;
            int idx = (cs + lane < e) ? g_colidx[cs + lane] : 0;
            int j = 0;
            for (; j + 4 <= cnt; j += 4) {
                int s0 = __shfl_sync(0xffffffffu, idx, j);
                int s1 = __shfl_sync(0xffffffffu, idx, j + 1);
                int s2 = __shfl_sync(0xffffffffu, idx, j + 2);
                int s3 = __shfl_sync(0xffffffffu, idx, j + 3);
                float2 v0 = __ldg(base + (size_t)s0 * 32 + lane);
                float2 v1 = __ldg(base + (size_t)s1 * 32 + lane);
                float2 v2 = __ldg(base + (size_t)s2 * 32 + lane);
                float2 v3 = __ldg(base + (size_t)s3 * 32 + lane);
                a0.x += v0.x; a0.y += v0.y;
                a1.x += v1.x; a1.y += v1.y;
                a2.x += v2.x; a2.y += v2.y;
                a3.x += v3.x; a3.y += v3.y;
            }
            for (; j < cnt; j++) {
                int s0 = __shfl_sync(0xffffffffu, idx, j);
                float2 v0 = __ldg(base + (size_t)s0 * 32 + lane);
                a1.x += v0.x; a1.y += v0.y;
            }
        }
        float accx = (a0.x + a1.x) + (a2.x + a3.x);
        float accy = (a0.y + a1.y) + (a2.y + a3.y);
        float di = g_dinv[node];
        float2 bv = __ldg((const float2*)bias + lane);
        float rx = di * accx + bv.x;
        float ry = di * accy + bv.y;
        int g = g_batch[node];
        if (lane == 0) { atomicMin(&s_gmin, g); atomicMax(&s_gmax, g); }
        atomicAdd(&spool[g * 64 + lane * 2], rx);
        atomicAdd(&spool[g * 64 + lane * 2 + 1], ry);
    }
    __syncthreads();
    int gmin = s_gmin, gmax = s_gmax;
    if (gmax >= gmin) {
        int lo = gmin * 64;
        int cnt = (gmax - gmin + 1) * 64;
        for (int j = tid; j < cnt; j += 256)
            atomicAdd(&g_gsum[lo + j], spool[lo + j]);
    }
}

__global__ void k_final(float* __restrict__ out, int n) {
    int i = blockIdx.x * blockDim.x + threadIdx.x;
    if (i < n) out[i] = g_gsum[i] / fmaxf(g_gcnt[i >> 6], 1.0f);
}

// ---------------- launch ----------------------------------------------------
extern "C" void kernel_launch(void* const* d_in, const int* in_sizes, int n_in,
                              void* d_out, int out_size) {
    const float* x  = (const float*)d_in[0];
    const void*  ei = d_in[1];
    const void*  bp = d_in[2];
    const float* W1 = (const float*)d_in[3];
    const float* b1 = (const float*)d_in[4];
    const float* W2 = (const float*)d_in[5];
    const float* b2 = (const float*)d_in[6];
    float* out = (float*)d_out;

    int N    = in_sizes[2];          // 50000
    int E    = in_sizes[1] / 2;      // 800000
    int din  = in_sizes[0] / N;      // 128
    int dhid = in_sizes[4];          // 128
    int dout = in_sizes[6];          // 64
    int NG   = out_size / dout;      // 64
    (void)dhid; (void)dout;

    float *p_xws1, *p_h, *p_xws2;
    cudaGetSymbolAddress((void**)&p_xws1, g_xws1);
    cudaGetSymbolAddress((void**)&p_h,    g_h);
    cudaGetSymbolAddress((void**)&p_xws2, g_xws2);

    int nbN = (N + 255) / 256;
    int nbE = (E + 255) / 256;
    int nbI = ((N > 4096 ? N : 4096) + 255) / 256;
    int nbS = (N + SCAN_CHUNK - 1) / SCAN_CHUNK;

    k_init<<<nbI, 256>>>(N);
    k_detect<<<1, 1>>>(ei);
    k_conv_edges_count<<<nbE, 256>>>(ei, E, N);
    k_conv_batch<<<nbN, 256>>>(bp, N, NG);
    k_scanA<<<nbS, SCAN_CHUNK>>>(N);
    k_scanB<<<1, 128>>>(nbS);
    k_scanC<<<nbS, SCAN_CHUNK>>>(N);
    k_fill<<<nbE, 256>>>(E);

    // layer 1
    gemm_kernel<128, 256><<<(N + 127) / 128, 256>>>(x, W1, p_xws1, N, din);
    agg1_kernel<<<(N + 7) / 8, 256>>>(p_xws1, b1, p_h, N);

    // layer 2 + fused pooling
    gemm_kernel<64, 128><<<(N + 127) / 128, 128>>>(p_h, W2, p_xws2, N, dhid);
    agg2_pool_kernel<<<(N + 7) / 8, 256>>>(p_xws2, b2, N);

    k_final<<<(out_size + 255) / 256, 256>>>(out, out_size);
}